// round 16
// baseline (speedup 1.0000x reference)
#include <cuda_runtime.h>
#include <cuda_fp16.h>
#include <math.h>
#include <stdint.h>

#define BZ    4
#define SEQ   256
#define DM    1024
#define HID   4096
#define VOCAB 32000
#define NH    16
#define DH    64
#define NL    6
#define ROWS  (BZ*SEQ)   // 1024

// ---------------- scratch (no allocations allowed) ----------------
__device__ float g_h   [ROWS*DM];
__device__ float g_q   [ROWS*DM];
__device__ float g_k   [ROWS*DM];
__device__ float g_v   [ROWS*DM];
__device__ float g_attn[ROWS*DM];
__device__ float g_proj[ROWS*DM];
__device__ float g_y   [ROWS*DM];
__device__ float g_y2  [ROWS*DM];
__device__ float g_ffn [ROWS*HID];
__device__ float g_ffn2[ROWS*DM];
__device__ float g_k2  [NL*ROWS*DM];
__device__ float g_v2  [NL*ROWS*DM];

// transposed half weights: [N][K] layout (B^T) for mma .col B operand
__device__ __half g_wq1h[NL*DM*DM];
__device__ __half g_wk1h[NL*DM*DM];
__device__ __half g_wv1h[NL*DM*DM];
__device__ __half g_wo1h[NL*DM*DM];
__device__ __half g_wq2h[NL*DM*DM];
__device__ __half g_wk2h[NL*DM*DM];
__device__ __half g_wv2h[NL*DM*DM];
__device__ __half g_wo2h[NL*DM*DM];
__device__ __half g_w1h [NL*(size_t)HID*DM];
__device__ __half g_w2h [NL*(size_t)DM*HID];
__device__ __half g_wouth[(size_t)VOCAB*DM];

struct PtrsN {
    const __half* B[12];
    float*        C[12];
};

// ---------------- helpers ----------------
__device__ __forceinline__ uint32_t f2tf32(float f) {
    uint32_t r;
    asm("cvt.rna.tf32.f32 %0, %1;" : "=r"(r) : "f"(f));
    return r;
}
__device__ __forceinline__ uint32_t f2h2(float lo, float hi) {
    uint32_t r;
    asm("cvt.rn.f16x2.f32 %0, %1, %2;" : "=r"(r) : "f"(hi), "f"(lo));
    return r;
}
__device__ __forceinline__ void mma_tf32(float c[4],
    uint32_t a0, uint32_t a1, uint32_t a2, uint32_t a3,
    uint32_t b0, uint32_t b1)
{
    asm("mma.sync.aligned.m16n8k8.row.col.f32.tf32.tf32.f32 "
        "{%0,%1,%2,%3},{%4,%5,%6,%7},{%8,%9},{%0,%1,%2,%3};"
        : "+f"(c[0]), "+f"(c[1]), "+f"(c[2]), "+f"(c[3])
        : "r"(a0), "r"(a1), "r"(a2), "r"(a3), "r"(b0), "r"(b1));
}
__device__ __forceinline__ void mma_f16(float c[4],
    uint32_t a0, uint32_t a1, uint32_t a2, uint32_t a3,
    uint32_t b0, uint32_t b1)
{
    asm("mma.sync.aligned.m16n8k16.row.col.f32.f16.f16.f32 "
        "{%0,%1,%2,%3},{%4,%5,%6,%7},{%8,%9},{%0,%1,%2,%3};"
        : "+f"(c[0]), "+f"(c[1]), "+f"(c[2]), "+f"(c[3])
        : "r"(a0), "r"(a1), "r"(a2), "r"(a3), "r"(b0), "r"(b1));
}

// ---------------- weight transpose+convert: out[n][k] = (half)in[k][n] ----------------
__global__ void transpose_h_kernel(const float* __restrict__ in, __half* __restrict__ out,
                                   int K, int N, size_t in_ls, size_t out_ls)
{
    __shared__ __half s[32][33];
    const float* ip = in + blockIdx.z * in_ls;
    __half*      op = out + blockIdx.z * out_ls;
    int n0 = blockIdx.x*32, k0 = blockIdx.y*32;
    int tx = threadIdx.x, ty = threadIdx.y;   // 32 x 8
    #pragma unroll
    for (int i = 0; i < 4; i++)
        s[ty + 8*i][tx] = __float2half_rn(ip[(size_t)(k0 + ty + 8*i)*N + n0 + tx]);
    __syncthreads();
    #pragma unroll
    for (int i = 0; i < 4; i++)
        op[(size_t)(n0 + ty + 8*i)*K + k0 + tx] = s[tx][ty + 8*i];
}

// ---------------- embedding + sinusoidal positional encoding ----------------
__global__ void embed_kernel(const int* __restrict__ X,
                             const float* __restrict__ emb,
                             float* __restrict__ h)
{
    int row = blockIdx.x;
    int s = row % SEQ;
    int tok = X[row];
    const float scale = 32.0f;
    const float l2 = 13.28771238f;
    for (int d = threadIdx.x; d < DM; d += blockDim.x) {
        int j = d & ~1;
        float freq = exp2f(-((float)j / (float)DM) * l2);
        float ang  = (float)s * freq;
        float sn, cs;
        sincosf(ang, &sn, &cs);
        float p = (d & 1) ? cs : sn;
        h[row*DM + d] = emb[tok*DM + d] * scale + p;
    }
}

// ---------------- fp16 tensor-core GEMM (round-14/15 winner, unchanged) ----------------
template<int WM, int WN, int MX>
__global__ void __launch_bounds__(WM*WN*32, (WM*WN == 4) ? 4 : ((WM*WN == 8) ? 2 : 1))
hgemm_kernel(const float* __restrict__ A, PtrsN P,
             const float* __restrict__ bias, int M, int N, int K, int relu)
{
    constexpr int BM  = WM*32;
    constexpr int BN  = WN*32;
    constexpr int T   = WM*WN*32;
    constexpr int ITA = BM*8 / T;
    constexpr int ITB = BN*4 / T;
    constexpr int SZA = BM*16;
    constexpr int SZB = BN*16;

    extern __shared__ __align__(16) uint32_t smem_u[];
    uint32_t* sA = smem_u;
    uint32_t* sB = smem_u + 2*SZA;

    const __half* __restrict__ Bp = P.B[blockIdx.z];
    float*        __restrict__ Cp = P.C[blockIdx.z];

    const int tid  = threadIdx.x;
    const int br   = (MX ? blockIdx.x : blockIdx.y) * BM;
    const int bc   = (MX ? blockIdx.y : blockIdx.x) * BN;
    const int wid  = tid >> 5;
    const int lane = tid & 31;
    const int wm   = wid / WN;
    const int wn   = wid % WN;
    const int rl   = lane >> 2;
    const int w    = lane & 3;

    float acc[2][4][4];
    #pragma unroll
    for (int im = 0; im < 2; im++)
        #pragma unroll
        for (int in = 0; in < 4; in++)
            #pragma unroll
            for (int t = 0; t < 4; t++) acc[im][in][t] = 0.f;

    float4 ra[ITA];
    uint4  rb[ITB];
    const int nkt = K >> 5;

    #pragma unroll
    for (int i = 0; i < ITA; i++) {
        int L = i*T + tid, m = L >> 3, c = L & 7;
        ra[i] = *(const float4*)&A[(size_t)(br+m)*K + c*4];
    }
    #pragma unroll
    for (int i = 0; i < ITB; i++) {
        int L = i*T + tid, n = L >> 2, c4 = L & 3;
        rb[i] = *(const uint4*)&Bp[(size_t)(bc+n)*K + c4*8];
    }
    #pragma unroll
    for (int i = 0; i < ITA; i++) {
        int L = i*T + tid, m = L >> 3, c = L & 7;
        uint2 u;
        u.x = f2h2(ra[i].x, ra[i].y);
        u.y = f2h2(ra[i].z, ra[i].w);
        *(uint2*)&sA[m*16 + ((c*2) ^ (((m>>1)&3)<<2))] = u;
    }
    #pragma unroll
    for (int i = 0; i < ITB; i++) {
        int L = i*T + tid, n = L >> 2, c4 = L & 3;
        *(uint4*)&sB[n*16 + ((c4*4) ^ (((n>>1)&3)<<2))] = rb[i];
    }
    __syncthreads();

    for (int kt = 0; kt < nkt; kt++) {
        const int st = kt & 1;
        if (kt + 1 < nkt) {
            int k0 = (kt + 1) << 5;
            #pragma unroll
            for (int i = 0; i < ITA; i++) {
                int L = i*T + tid, m = L >> 3, c = L & 7;
                ra[i] = *(const float4*)&A[(size_t)(br+m)*K + k0 + c*4];
            }
            #pragma unroll
            for (int i = 0; i < ITB; i++) {
                int L = i*T + tid, n = L >> 2, c4 = L & 3;
                rb[i] = *(const uint4*)&Bp[(size_t)(bc+n)*K + k0 + c4*8];
            }
        }

        const uint32_t* __restrict__ pA = sA + st*SZA;
        const uint32_t* __restrict__ pB = sB + st*SZB;
        #pragma unroll
        for (int kc = 0; kc < 2; kc++) {
            const int p0 = kc*8 + w;
            const int p1 = p0 + 4;
            uint32_t a[2][4], b[4][2];
            #pragma unroll
            for (int im = 0; im < 2; im++) {
                int r  = wm*32 + im*16 + rl;
                int sz = ((r>>1)&3)<<2;
                a[im][0] = pA[ r     *16 + (p0 ^ sz)];
                a[im][1] = pA[(r + 8)*16 + (p0 ^ sz)];
                a[im][2] = pA[ r     *16 + (p1 ^ sz)];
                a[im][3] = pA[(r + 8)*16 + (p1 ^ sz)];
            }
            #pragma unroll
            for (int in = 0; in < 4; in++) {
                int n  = wn*32 + in*8 + rl;
                int sz = ((n>>1)&3)<<2;
                b[in][0] = pB[n*16 + (p0 ^ sz)];
                b[in][1] = pB[n*16 + (p1 ^ sz)];
            }
            #pragma unroll
            for (int im = 0; im < 2; im++)
                #pragma unroll
                for (int in = 0; in < 4; in++)
                    mma_f16(acc[im][in], a[im][0], a[im][1], a[im][2], a[im][3],
                            b[in][0], b[in][1]);
        }

        if (kt + 1 < nkt) {
            const int sn = st ^ 1;
            #pragma unroll
            for (int i = 0; i < ITA; i++) {
                int L = i*T + tid, m = L >> 3, c = L & 7;
                uint2 u;
                u.x = f2h2(ra[i].x, ra[i].y);
                u.y = f2h2(ra[i].z, ra[i].w);
                *(uint2*)&sA[sn*SZA + m*16 + ((c*2) ^ (((m>>1)&3)<<2))] = u;
            }
            #pragma unroll
            for (int i = 0; i < ITB; i++) {
                int L = i*T + tid, n = L >> 2, c4 = L & 3;
                *(uint4*)&sB[sn*SZB + n*16 + ((c4*4) ^ (((n>>1)&3)<<2))] = rb[i];
            }
        }
        __syncthreads();
    }

    const int r0 = br + wm*32 + rl;
    const int c0 = bc + wn*32 + w*2;
    #pragma unroll
    for (int im = 0; im < 2; im++) {
        int r = r0 + im*16;
        #pragma unroll
        for (int in = 0; in < 4; in++) {
            int c = c0 + in*8;
            float2 v0 = make_float2(acc[im][in][0], acc[im][in][1]);
            float2 v1 = make_float2(acc[im][in][2], acc[im][in][3]);
            if (bias) {
                float b0 = bias[c], b1 = bias[c+1];
                v0.x += b0; v0.y += b1; v1.x += b0; v1.y += b1;
            }
            if (relu) {
                v0.x = fmaxf(v0.x, 0.f); v0.y = fmaxf(v0.y, 0.f);
                v1.x = fmaxf(v1.x, 0.f); v1.y = fmaxf(v1.y, 0.f);
            }
            *(float2*)&Cp[(size_t)r     * N + c] = v0;
            *(float2*)&Cp[(size_t)(r+8) * N + c] = v1;
        }
    }
}

#define HS_22 ((2*(64*16)  + 2*(64*16))  * 4)   // 16 KB

static void hgemm64(const float* A, const __half* B, const float* bias, float* C,
                    int M, int N, int K, int relu)
{
    PtrsN P; P.B[0]=B; P.C[0]=C;
    dim3 grid(N/64, M/64, 1);
    hgemm_kernel<2,2,0><<<grid, 128, HS_22>>>(A, P, bias, M, N, K, relu);
}
static void hgemm_big(const float* A, PtrsN P, const float* bias, int z,
                      int M, int N, int K, int relu)
{
    dim3 grid(M/64, N/64, z);
    hgemm_kernel<2,2,1><<<grid, 128, HS_22>>>(A, P, bias, M, N, K, relu);
}

// ---------------- fused flash attention: 32-q-row tiles, 3 CTAs/SM ----------------
// Same math/layout as round-7; round-11-proven warp partition:
// wq=(wid&1)*16 selects q-block, jh=wid>>1 selects n/d tile-half.
#define PS  68
#define PSC 260
#define FLASH_SMEM ((32*PS + 64*PS + 32*PSC) * 4)   // 59.4 KB

__global__ void __launch_bounds__(128)
flash_attn_kernel(const float* __restrict__ Q, const float* __restrict__ Kv,
                  const float* __restrict__ Vv, float* __restrict__ O,
                  const int* __restrict__ valid, int mode)
{
    extern __shared__ uint32_t sm[];
    uint32_t* Qs  = sm;                    // [32][PS]
    uint32_t* KVs = sm + 32*PS;            // [64][PS]
    float*    Sc  = (float*)(sm + 32*PS + 64*PS);  // [32][PSC]

    const int bh = blockIdx.y, b = bh >> 4, h = bh & 15;
    const int i0 = blockIdx.x * 32;
    const int tid = threadIdx.x;
    const int wid = tid >> 5, lane = tid & 31;
    const int rl = lane >> 2, w = lane & 3;
    const int wq = (wid & 1) * 16;   // q-block within the 32-row tile
    const int jh = wid >> 1;         // n/d tile half: tiles [jh*4, jh*4+4)

    for (int t = tid; t < 32*16; t += 128) {
        int r = t >> 4, c4 = t & 15;
        float4 f = *(const float4*)&Q[(size_t)(b*SEQ + i0 + r)*DM + h*DH + c4*4];
        uint4 u;
        u.x = f2tf32(f.x); u.y = f2tf32(f.y); u.z = f2tf32(f.z); u.w = f2tf32(f.w);
        *(uint4*)&Qs[r*PS + c4*4] = u;
    }

    const int vb = valid[b];
    const int iA = i0 + wq + rl;
    const int iB = iA + 8;
    const int vldA = (mode == 0) ? min(vb, iA + 1) : vb;
    const int vldB = (mode == 0) ? min(vb, iB + 1) : vb;

    // ---- phase 1: scores ----
    for (int j0 = 0; j0 < SEQ; j0 += 64) {
        __syncthreads();
        for (int t = tid; t < 64*16; t += 128) {
            int r = t >> 4, c4 = t & 15;
            float4 f = *(const float4*)&Kv[(size_t)(b*SEQ + j0 + r)*DM + h*DH + c4*4];
            uint4 u;
            u.x = f2tf32(f.x); u.y = f2tf32(f.y); u.z = f2tf32(f.z); u.w = f2tf32(f.w);
            *(uint4*)&KVs[r*PS + c4*4] = u;
        }
        __syncthreads();

        float acc[4][4];
        #pragma unroll
        for (int nt = 0; nt < 4; nt++)
            #pragma unroll
            for (int t = 0; t < 4; t++) acc[nt][t] = 0.f;

        #pragma unroll
        for (int kk = 0; kk < 8; kk++) {
            int k0 = kk * 8;
            uint32_t a0 = Qs[(wq + rl    )*PS + k0 + w];
            uint32_t a1 = Qs[(wq + rl + 8)*PS + k0 + w];
            uint32_t a2 = Qs[(wq + rl    )*PS + k0 + w + 4];
            uint32_t a3 = Qs[(wq + rl + 8)*PS + k0 + w + 4];
            #pragma unroll
            for (int nt = 0; nt < 4; nt++) {
                int ntg = jh*4 + nt;
                uint32_t b0 = KVs[(ntg*8 + rl)*PS + k0 + w];
                uint32_t b1 = KVs[(ntg*8 + rl)*PS + k0 + w + 4];
                mma_tf32(acc[nt], a0, a1, a2, a3, b0, b1);
            }
        }

        #pragma unroll
        for (int nt = 0; nt < 4; nt++) {
            int j = j0 + (jh*4 + nt)*8 + w*2;
            float2 v0, v1;
            v0.x = (j     >= vldA) ? 1e-6f : acc[nt][0]*0.125f;
            v0.y = (j + 1 >= vldA) ? 1e-6f : acc[nt][1]*0.125f;
            v1.x = (j     >= vldB) ? 1e-6f : acc[nt][2]*0.125f;
            v1.y = (j + 1 >= vldB) ? 1e-6f : acc[nt][3]*0.125f;
            *(float2*)&Sc[(wq + rl    )*PSC + j] = v0;
            *(float2*)&Sc[(wq + rl + 8)*PSC + j] = v1;
        }
    }
    __syncthreads();

    // ---- phase 2: softmax, 8 rows per warp ----
    for (int rr = 0; rr < 8; rr++) {
        float* p = Sc + (wid*8 + rr)*PSC;
        float vals[8];
        float mx = -1e30f;
        #pragma unroll
        for (int t = 0; t < 8; t++) { vals[t] = p[lane + t*32]; mx = fmaxf(mx, vals[t]); }
        #pragma unroll
        for (int o = 16; o; o >>= 1) mx = fmaxf(mx, __shfl_xor_sync(0xffffffffu, mx, o));
        float sum = 0.f;
        #pragma unroll
        for (int t = 0; t < 8; t++) { vals[t] = expf(vals[t] - mx); sum += vals[t]; }
        #pragma unroll
        for (int o = 16; o; o >>= 1) sum += __shfl_xor_sync(0xffffffffu, sum, o);
        float inv = 1.0f / sum;
        #pragma unroll
        for (int t = 0; t < 8; t++) p[lane + t*32] = vals[t] * inv;
    }

    // ---- phase 3: O = P @ V ----
    float oacc[4][4];
    #pragma unroll
    for (int nt = 0; nt < 4; nt++)
        #pragma unroll
        for (int t = 0; t < 4; t++) oacc[nt][t] = 0.f;

    for (int j0 = 0; j0 < SEQ; j0 += 64) {
        __syncthreads();
        for (int t = tid; t < 64*16; t += 128) {
            int j = t >> 4, c4 = t & 15;
            float4 f = *(const float4*)&Vv[(size_t)(b*SEQ + j0 + j)*DM + h*DH + c4*4];
            int d0 = c4*4;
            KVs[(d0  )*PS + (j ^ (((d0  )>>2)&15))] = f2tf32(f.x);
            KVs[(d0+1)*PS + (j ^ (((d0+1)>>2)&15))] = f2tf32(f.y);
            KVs[(d0+2)*PS + (j ^ (((d0+2)>>2)&15))] = f2tf32(f.z);
            KVs[(d0+3)*PS + (j ^ (((d0+3)>>2)&15))] = f2tf32(f.w);
        }
        __syncthreads();

        #pragma unroll
        for (int kk = 0; kk < 8; kk++) {
            int k0 = kk * 8;
            uint32_t a0 = f2tf32(Sc[(wq + rl    )*PSC + j0 + k0 + w]);
            uint32_t a1 = f2tf32(Sc[(wq + rl + 8)*PSC + j0 + k0 + w]);
            uint32_t a2 = f2tf32(Sc[(wq + rl    )*PSC + j0 + k0 + w + 4]);
            uint32_t a3 = f2tf32(Sc[(wq + rl + 8)*PSC + j0 + k0 + w + 4]);
            #pragma unroll
            for (int nt = 0; nt < 4; nt++) {
                int d  = (jh*4 + nt)*8 + rl;
                int fx = (d >> 2) & 15;
                uint32_t b0 = KVs[d*PS + ((k0 + w    ) ^ fx)];
                uint32_t b1 = KVs[d*PS + ((k0 + w + 4) ^ fx)];
                mma_tf32(oacc[nt], a0, a1, a2, a3, b0, b1);
            }
        }
    }

    #pragma unroll
    for (int nt = 0; nt < 4; nt++) {
        int d = (jh*4 + nt)*8 + w*2;
        *(float2*)&O[(size_t)(b*SEQ + iA)*DM + h*DH + d] = make_float2(oacc[nt][0], oacc[nt][1]);
        *(float2*)&O[(size_t)(b*SEQ + iB)*DM + h*DH + d] = make_float2(oacc[nt][2], oacc[nt][3]);
    }
}

// ---------------- out = LayerNorm(a + r) * g + be ----------------
__global__ void add_ln_kernel(const float* __restrict__ a, const float* __restrict__ r,
                              const float* __restrict__ g, const float* __restrict__ be,
                              float* __restrict__ out)
{
    int row = blockIdx.x;
    __shared__ float red[256];
    float x[4];
    #pragma unroll
    for (int t = 0; t < 4; t++) {
        int c = threadIdx.x + t*256;
        x[t] = a[row*DM + c] + r[row*DM + c];
    }
    float s = x[0] + x[1] + x[2] + x[3];
    red[threadIdx.x] = s; __syncthreads();
    for (int o = 128; o; o >>= 1) {
        if (threadIdx.x < o) red[threadIdx.x] += red[threadIdx.x + o];
        __syncthreads();
    }
    float mean = red[0] * (1.0f / DM);
    __syncthreads();
    float vs = 0.f;
    #pragma unroll
    for (int t = 0; t < 4; t++) { float d = x[t] - mean; vs += d*d; }
    red[threadIdx.x] = vs; __syncthreads();
    for (int o = 128; o; o >>= 1) {
        if (threadIdx.x < o) red[threadIdx.x] += red[threadIdx.x + o];
        __syncthreads();
    }
    float inv = rsqrtf(red[0] * (1.0f / DM) + 1e-5f);
    #pragma unroll
    for (int t = 0; t < 4; t++) {
        int c = threadIdx.x + t*256;
        out[row*DM + c] = (x[t] - mean) * inv * g[c] + be[c];
    }
}

// ---------------- host orchestration ----------------
extern "C" void kernel_launch(void* const* d_in, const int* in_sizes, int n_in,
                              void* d_out, int out_size)
{
    const int*   X         = (const int*)  d_in[0];
    const int*   dec_valid = (const int*)  d_in[1];
    const float* enc_out   = (const float*)d_in[2];
    const int*   enc_valid = (const int*)  d_in[3];
    const float* emb       = (const float*)d_in[4];
    const float* Wq1 = (const float*)d_in[5];
    const float* Wk1 = (const float*)d_in[6];
    const float* Wv1 = (const float*)d_in[7];
    const float* Wo1 = (const float*)d_in[8];
    const float* Wq2 = (const float*)d_in[9];
    const float* Wk2 = (const float*)d_in[10];
    const float* Wv2 = (const float*)d_in[11];
    const float* Wo2 = (const float*)d_in[12];
    const float* W1  = (const float*)d_in[13];
    const float* W2  = (const float*)d_in[14];
    const float* Wout= (const float*)d_in[15];
    const float* b1  = (const float*)d_in[16];
    const float* b2  = (const float*)d_in[17];
    const float* bout= (const float*)d_in[18];
    const float* ln1g= (const float*)d_in[19];
    const float* ln1b= (const float*)d_in[20];
    const float* ln2g= (const float*)d_in[21];
    const float* ln2b= (const float*)d_in[22];
    const float* ln3g= (const float*)d_in[23];
    const float* ln3b= (const float*)d_in[24];
    float* out = (float*)d_out;

    float *h, *q, *k, *v, *attn, *proj, *y, *y2, *ffn, *ffn2, *k2, *v2;
    cudaGetSymbolAddress((void**)&h,    g_h);
    cudaGetSymbolAddress((void**)&q,    g_q);
    cudaGetSymbolAddress((void**)&k,    g_k);
    cudaGetSymbolAddress((void**)&v,    g_v);
    cudaGetSymbolAddress((void**)&attn, g_attn);
    cudaGetSymbolAddress((void**)&proj, g_proj);
    cudaGetSymbolAddress((void**)&y,    g_y);
    cudaGetSymbolAddress((void**)&y2,   g_y2);
    cudaGetSymbolAddress((void**)&ffn,  g_ffn);
    cudaGetSymbolAddress((void**)&ffn2, g_ffn2);
    cudaGetSymbolAddress((void**)&k2,   g_k2);
    cudaGetSymbolAddress((void**)&v2,   g_v2);

    __half *wq1h, *wk1h, *wv1h, *wo1h, *wq2h, *wk2h, *wv2h, *wo2h, *w1h, *w2h, *wouth;
    cudaGetSymbolAddress((void**)&wq1h, g_wq1h);
    cudaGetSymbolAddress((void**)&wk1h, g_wk1h);
    cudaGetSymbolAddress((void**)&wv1h, g_wv1h);
    cudaGetSymbolAddress((void**)&wo1h, g_wo1h);
    cudaGetSymbolAddress((void**)&wq2h, g_wq2h);
    cudaGetSymbolAddress((void**)&wk2h, g_wk2h);
    cudaGetSymbolAddress((void**)&wv2h, g_wv2h);
    cudaGetSymbolAddress((void**)&wo2h, g_wo2h);
    cudaGetSymbolAddress((void**)&w1h,  g_w1h);
    cudaGetSymbolAddress((void**)&w2h,  g_w2h);
    cudaGetSymbolAddress((void**)&wouth,g_wouth);

    static int attr_set = 0;
    if (!attr_set) {
        cudaFuncSetAttribute(flash_attn_kernel,
                             cudaFuncAttributeMaxDynamicSharedMemorySize, FLASH_SMEM);
        attr_set = 1;
    }

    // ---- weight transpose+convert ----
    {
        dim3 tb(32, 8);
        dim3 gsq(DM/32, DM/32, NL);
        size_t sq = (size_t)DM*DM;
        transpose_h_kernel<<<gsq, tb>>>(Wq1, wq1h, DM, DM, sq, sq);
        transpose_h_kernel<<<gsq, tb>>>(Wk1, wk1h, DM, DM, sq, sq);
        transpose_h_kernel<<<gsq, tb>>>(Wv1, wv1h, DM, DM, sq, sq);
        transpose_h_kernel<<<gsq, tb>>>(Wo1, wo1h, DM, DM, sq, sq);
        transpose_h_kernel<<<gsq, tb>>>(Wq2, wq2h, DM, DM, sq, sq);
        transpose_h_kernel<<<gsq, tb>>>(Wk2, wk2h, DM, DM, sq, sq);
        transpose_h_kernel<<<gsq, tb>>>(Wv2, wv2h, DM, DM, sq, sq);
        transpose_h_kernel<<<gsq, tb>>>(Wo2, wo2h, DM, DM, sq, sq);
        size_t rct = (size_t)DM*HID;
        transpose_h_kernel<<<dim3(HID/32, DM/32, NL), tb>>>(W1, w1h, DM, HID, rct, rct);
        transpose_h_kernel<<<dim3(DM/32, HID/32, NL), tb>>>(W2, w2h, HID, DM, rct, rct);
        transpose_h_kernel<<<dim3(VOCAB/32, DM/32, 1), tb>>>(Wout, wouth, DM, VOCAB, 0, 0);
    }

    embed_kernel<<<ROWS, 256>>>(X, emb, h);

    // hoisted cross-attention K/V projections for ALL layers
    {
        PtrsN P;
        for (int l = 0; l < NL; l++) {
            P.B[l*2  ] = wk2h + (size_t)l*DM*DM;
            P.B[l*2+1] = wv2h + (size_t)l*DM*DM;
            P.C[l*2  ] = k2 + (size_t)l*ROWS*DM;
            P.C[l*2+1] = v2 + (size_t)l*ROWS*DM;
        }
        hgemm_big(enc_out, P, nullptr, 2*NL, ROWS, DM, DM, 0);
    }

    dim3 fgrid(SEQ/32, BZ*NH);   // 8 x 64 = 512 CTAs

    for (int l = 0; l < NL; l++) {
        const size_t o2 = (size_t)l*DM*DM;
        // ---- self attention ----
        {
            PtrsN P;
            P.B[0]=wq1h+o2; P.B[1]=wk1h+o2; P.B[2]=wv1h+o2;
            P.C[0]=q;       P.C[1]=k;       P.C[2]=v;
            hgemm_big(h, P, nullptr, 3, ROWS, DM, DM, 0);
        }
        flash_attn_kernel<<<fgrid, 128, FLASH_SMEM>>>(q, k, v, attn, dec_valid, 0);
        hgemm64(attn, wo1h+o2, nullptr, proj, ROWS, DM, DM, 0);
        add_ln_kernel<<<ROWS, 256>>>(h, proj, ln1g + l*DM, ln1b + l*DM, y);
        // ---- cross attention (K/V precomputed) ----
        hgemm64(y, wq2h+o2, nullptr, q, ROWS, DM, DM, 0);
        flash_attn_kernel<<<fgrid, 128, FLASH_SMEM>>>(
            q, k2 + (size_t)l*ROWS*DM, v2 + (size_t)l*ROWS*DM, attn, enc_valid, 1);
        hgemm64(attn, wo2h+o2, nullptr, proj, ROWS, DM, DM, 0);
        add_ln_kernel<<<ROWS, 256>>>(y, proj, ln2g + l*DM, ln2b + l*DM, y2);
        // ---- FFN ----
        {
            PtrsN P;
            P.B[0] = w1h + (size_t)l*HID*DM;
            P.C[0] = ffn;
            hgemm_big(y2, P, b1 + l*HID, 1, ROWS, HID, DM, 1);
        }
        hgemm64(ffn, w2h + (size_t)l*DM*HID, b2 + l*DM, ffn2, ROWS, DM, HID, 0);
        add_ln_kernel<<<ROWS, 256>>>(y2, ffn2, ln3g + l*DM, ln3b + l*DM, h);
    }
    // ---- final vocab projection ----
    {
        PtrsN P;
        P.B[0] = wouth;
        P.C[0] = out;
        hgemm_big(h, P, bout, 1, ROWS, VOCAB, DM, 0);
    }
}

// round 17
// speedup vs baseline: 1.0989x; 1.0989x over previous
#include <cuda_runtime.h>
#include <cuda_fp16.h>
#include <math.h>
#include <stdint.h>

#define BZ    4
#define SEQ   256
#define DM    1024
#define HID   4096
#define VOCAB 32000
#define NH    16
#define DH    64
#define NL    6
#define ROWS  (BZ*SEQ)   // 1024

// ---------------- scratch (no allocations allowed) ----------------
__device__ float g_h    [ROWS*DM];
__device__ float g_q    [ROWS*DM];
__device__ float g_k    [ROWS*DM];
__device__ float g_v    [ROWS*DM];
__device__ float g_attn [ROWS*DM];
__device__ float g_proj [ROWS*DM];
__device__ float g_proj2[ROWS*DM];
__device__ float g_y    [ROWS*DM];
__device__ float g_y2   [ROWS*DM];
__device__ float g_ffn  [ROWS*HID];
__device__ float g_k2   [NL*ROWS*DM];
__device__ float g_v2   [NL*ROWS*DM];

// transposed half weights: [N][K] layout (B^T) for mma .col B operand
__device__ __half g_wq1h[NL*DM*DM];
__device__ __half g_wk1h[NL*DM*DM];
__device__ __half g_wv1h[NL*DM*DM];
__device__ __half g_wo1h[NL*DM*DM];
__device__ __half g_wq2h[NL*DM*DM];
__device__ __half g_wk2h[NL*DM*DM];
__device__ __half g_wv2h[NL*DM*DM];
__device__ __half g_wo2h[NL*DM*DM];
__device__ __half g_w1h [NL*(size_t)HID*DM];
__device__ __half g_w2h [NL*(size_t)DM*HID];
__device__ __half g_wouth[(size_t)VOCAB*DM];

struct PtrsN {
    const __half* B[12];
    float*        C[12];
};

// ---------------- helpers ----------------
__device__ __forceinline__ uint32_t f2tf32(float f) {
    uint32_t r;
    asm("cvt.rna.tf32.f32 %0, %1;" : "=r"(r) : "f"(f));
    return r;
}
__device__ __forceinline__ uint32_t f2h2(float lo, float hi) {
    uint32_t r;
    asm("cvt.rn.f16x2.f32 %0, %1, %2;" : "=r"(r) : "f"(hi), "f"(lo));
    return r;
}
__device__ __forceinline__ void mma_tf32(float c[4],
    uint32_t a0, uint32_t a1, uint32_t a2, uint32_t a3,
    uint32_t b0, uint32_t b1)
{
    asm("mma.sync.aligned.m16n8k8.row.col.f32.tf32.tf32.f32 "
        "{%0,%1,%2,%3},{%4,%5,%6,%7},{%8,%9},{%0,%1,%2,%3};"
        : "+f"(c[0]), "+f"(c[1]), "+f"(c[2]), "+f"(c[3])
        : "r"(a0), "r"(a1), "r"(a2), "r"(a3), "r"(b0), "r"(b1));
}
__device__ __forceinline__ void mma_f16(float c[4],
    uint32_t a0, uint32_t a1, uint32_t a2, uint32_t a3,
    uint32_t b0, uint32_t b1)
{
    asm("mma.sync.aligned.m16n8k16.row.col.f32.f16.f16.f32 "
        "{%0,%1,%2,%3},{%4,%5,%6,%7},{%8,%9},{%0,%1,%2,%3};"
        : "+f"(c[0]), "+f"(c[1]), "+f"(c[2]), "+f"(c[3])
        : "r"(a0), "r"(a1), "r"(a2), "r"(a3), "r"(b0), "r"(b1));
}

// ---------------- weight transpose+convert: out[n][k] = (half)in[k][n] ----------------
__global__ void transpose_h_kernel(const float* __restrict__ in, __half* __restrict__ out,
                                   int K, int N, size_t in_ls, size_t out_ls)
{
    __shared__ __half s[32][33];
    const float* ip = in + blockIdx.z * in_ls;
    __half*      op = out + blockIdx.z * out_ls;
    int n0 = blockIdx.x*32, k0 = blockIdx.y*32;
    int tx = threadIdx.x, ty = threadIdx.y;   // 32 x 8
    #pragma unroll
    for (int i = 0; i < 4; i++)
        s[ty + 8*i][tx] = __float2half_rn(ip[(size_t)(k0 + ty + 8*i)*N + n0 + tx]);
    __syncthreads();
    #pragma unroll
    for (int i = 0; i < 4; i++)
        op[(size_t)(n0 + ty + 8*i)*K + k0 + tx] = s[tx][ty + 8*i];
}

// ---------------- embedding + sinusoidal positional encoding ----------------
__global__ void embed_kernel(const int* __restrict__ X,
                             const float* __restrict__ emb,
                             float* __restrict__ h)
{
    int row = blockIdx.x;
    int s = row % SEQ;
    int tok = X[row];
    const float scale = 32.0f;
    const float l2 = 13.28771238f;
    for (int d = threadIdx.x; d < DM; d += blockDim.x) {
        int j = d & ~1;
        float freq = exp2f(-((float)j / (float)DM) * l2);
        float ang  = (float)s * freq;
        float sn, cs;
        sincosf(ang, &sn, &cs);
        float p = (d & 1) ? cs : sn;
        h[row*DM + d] = emb[tok*DM + d] * scale + p;
    }
}

// ---------------- fp16 tensor-core GEMM (round-14/15 dataflow + split-K option) ----------------
// KS=1: grid.z selects K-half (koff = z*K); C[z] gets the partial; bias only on z==0.
// lda = row stride of A and B (full K); K = loop extent.
template<int WM, int WN, int MX, int KS>
__global__ void __launch_bounds__(WM*WN*32, (WM*WN == 4) ? 4 : ((WM*WN == 8) ? 2 : 1))
hgemm_kernel(const float* __restrict__ A, PtrsN P,
             const float* __restrict__ bias, int M, int N, int K, int relu, int lda)
{
    constexpr int BM  = WM*32;
    constexpr int BN  = WN*32;
    constexpr int T   = WM*WN*32;
    constexpr int ITA = BM*8 / T;
    constexpr int ITB = BN*4 / T;
    constexpr int SZA = BM*16;
    constexpr int SZB = BN*16;

    extern __shared__ __align__(16) uint32_t smem_u[];
    uint32_t* sA = smem_u;
    uint32_t* sB = smem_u + 2*SZA;

    const int koff = KS ? (int)blockIdx.z * K : 0;
    const float*  __restrict__ Ap = A + koff;
    const __half* __restrict__ Bp = P.B[KS ? 0 : blockIdx.z] + koff;
    float*        __restrict__ Cp = P.C[blockIdx.z];
    const float*  bp = (KS && blockIdx.z != 0) ? nullptr : bias;

    const int tid  = threadIdx.x;
    const int br   = (MX ? blockIdx.x : blockIdx.y) * BM;
    const int bc   = (MX ? blockIdx.y : blockIdx.x) * BN;
    const int wid  = tid >> 5;
    const int lane = tid & 31;
    const int wm   = wid / WN;
    const int wn   = wid % WN;
    const int rl   = lane >> 2;
    const int w    = lane & 3;

    float acc[2][4][4];
    #pragma unroll
    for (int im = 0; im < 2; im++)
        #pragma unroll
        for (int in = 0; in < 4; in++)
            #pragma unroll
            for (int t = 0; t < 4; t++) acc[im][in][t] = 0.f;

    float4 ra[ITA];
    uint4  rb[ITB];
    const int nkt = K >> 5;

    #pragma unroll
    for (int i = 0; i < ITA; i++) {
        int L = i*T + tid, m = L >> 3, c = L & 7;
        ra[i] = *(const float4*)&Ap[(size_t)(br+m)*lda + c*4];
    }
    #pragma unroll
    for (int i = 0; i < ITB; i++) {
        int L = i*T + tid, n = L >> 2, c4 = L & 3;
        rb[i] = *(const uint4*)&Bp[(size_t)(bc+n)*lda + c4*8];
    }
    #pragma unroll
    for (int i = 0; i < ITA; i++) {
        int L = i*T + tid, m = L >> 3, c = L & 7;
        uint2 u;
        u.x = f2h2(ra[i].x, ra[i].y);
        u.y = f2h2(ra[i].z, ra[i].w);
        *(uint2*)&sA[m*16 + ((c*2) ^ (((m>>1)&3)<<2))] = u;
    }
    #pragma unroll
    for (int i = 0; i < ITB; i++) {
        int L = i*T + tid, n = L >> 2, c4 = L & 3;
        *(uint4*)&sB[n*16 + ((c4*4) ^ (((n>>1)&3)<<2))] = rb[i];
    }
    __syncthreads();

    for (int kt = 0; kt < nkt; kt++) {
        const int st = kt & 1;
        if (kt + 1 < nkt) {
            int k0 = (kt + 1) << 5;
            #pragma unroll
            for (int i = 0; i < ITA; i++) {
                int L = i*T + tid, m = L >> 3, c = L & 7;
                ra[i] = *(const float4*)&Ap[(size_t)(br+m)*lda + k0 + c*4];
            }
            #pragma unroll
            for (int i = 0; i < ITB; i++) {
                int L = i*T + tid, n = L >> 2, c4 = L & 3;
                rb[i] = *(const uint4*)&Bp[(size_t)(bc+n)*lda + k0 + c4*8];
            }
        }

        const uint32_t* __restrict__ pA = sA + st*SZA;
        const uint32_t* __restrict__ pB = sB + st*SZB;
        #pragma unroll
        for (int kc = 0; kc < 2; kc++) {
            const int p0 = kc*8 + w;
            const int p1 = p0 + 4;
            uint32_t a[2][4], b[4][2];
            #pragma unroll
            for (int im = 0; im < 2; im++) {
                int r  = wm*32 + im*16 + rl;
                int sz = ((r>>1)&3)<<2;
                a[im][0] = pA[ r     *16 + (p0 ^ sz)];
                a[im][1] = pA[(r + 8)*16 + (p0 ^ sz)];
                a[im][2] = pA[ r     *16 + (p1 ^ sz)];
                a[im][3] = pA[(r + 8)*16 + (p1 ^ sz)];
            }
            #pragma unroll
            for (int in = 0; in < 4; in++) {
                int n  = wn*32 + in*8 + rl;
                int sz = ((n>>1)&3)<<2;
                b[in][0] = pB[n*16 + (p0 ^ sz)];
                b[in][1] = pB[n*16 + (p1 ^ sz)];
            }
            #pragma unroll
            for (int im = 0; im < 2; im++)
                #pragma unroll
                for (int in = 0; in < 4; in++)
                    mma_f16(acc[im][in], a[im][0], a[im][1], a[im][2], a[im][3],
                            b[in][0], b[in][1]);
        }

        if (kt + 1 < nkt) {
            const int sn = st ^ 1;
            #pragma unroll
            for (int i = 0; i < ITA; i++) {
                int L = i*T + tid, m = L >> 3, c = L & 7;
                uint2 u;
                u.x = f2h2(ra[i].x, ra[i].y);
                u.y = f2h2(ra[i].z, ra[i].w);
                *(uint2*)&sA[sn*SZA + m*16 + ((c*2) ^ (((m>>1)&3)<<2))] = u;
            }
            #pragma unroll
            for (int i = 0; i < ITB; i++) {
                int L = i*T + tid, n = L >> 2, c4 = L & 3;
                *(uint4*)&sB[sn*SZB + n*16 + ((c4*4) ^ (((n>>1)&3)<<2))] = rb[i];
            }
        }
        __syncthreads();
    }

    const int r0 = br + wm*32 + rl;
    const int c0 = bc + wn*32 + w*2;
    #pragma unroll
    for (int im = 0; im < 2; im++) {
        int r = r0 + im*16;
        #pragma unroll
        for (int in = 0; in < 4; in++) {
            int c = c0 + in*8;
            float2 v0 = make_float2(acc[im][in][0], acc[im][in][1]);
            float2 v1 = make_float2(acc[im][in][2], acc[im][in][3]);
            if (bp) {
                float b0 = bp[c], b1 = bp[c+1];
                v0.x += b0; v0.y += b1; v1.x += b0; v1.y += b1;
            }
            if (relu) {
                v0.x = fmaxf(v0.x, 0.f); v0.y = fmaxf(v0.y, 0.f);
                v1.x = fmaxf(v1.x, 0.f); v1.y = fmaxf(v1.y, 0.f);
            }
            *(float2*)&Cp[(size_t)r     * N + c] = v0;
            *(float2*)&Cp[(size_t)(r+8) * N + c] = v1;
        }
    }
}

#define HS_22 ((2*(64*16)  + 2*(64*16))  * 4)   // 16 KB

static void hgemm64(const float* A, const __half* B, const float* bias, float* C,
                    int M, int N, int K, int relu)
{
    PtrsN P; P.B[0]=B; P.C[0]=C;
    dim3 grid(N/64, M/64, 1);
    hgemm_kernel<2,2,0,0><<<grid, 128, HS_22>>>(A, P, bias, M, N, K, relu, K);
}
// split-K x2: C0/C1 get the two K-half partials (bias folded into C0)
static void hgemm64ks(const float* A, const __half* B, const float* bias,
                      float* C0, float* C1, int M, int N, int Kfull)
{
    PtrsN P; P.B[0]=B; P.C[0]=C0; P.C[1]=C1;
    dim3 grid(N/64, M/64, 2);
    hgemm_kernel<2,2,0,1><<<grid, 128, HS_22>>>(A, P, bias, M, N, Kfull/2, 0, Kfull);
}
static void hgemm_big(const float* A, PtrsN P, const float* bias, int z,
                      int M, int N, int K, int relu)
{
    dim3 grid(M/64, N/64, z);
    hgemm_kernel<2,2,1,0><<<grid, 128, HS_22>>>(A, P, bias, M, N, K, relu, K);
}

// ---------------- fused flash attention (round-15 winner: 64-row, 4 warps) ----------------
#define PS  68
#define PSC 260
#define FLASH_SMEM ((2*64*PS + 64*PSC) * 4)

__global__ void __launch_bounds__(128)
flash_attn_kernel(const float* __restrict__ Q, const float* __restrict__ Kv,
                  const float* __restrict__ Vv, float* __restrict__ O,
                  const int* __restrict__ valid, int mode)
{
    extern __shared__ uint32_t sm[];
    uint32_t* Qs  = sm;
    uint32_t* KVs = sm + 64*PS;
    float*    Sc  = (float*)(sm + 2*64*PS);

    const int bh = blockIdx.y, b = bh >> 4, h = bh & 15;
    const int i0 = blockIdx.x * 64;
    const int tid = threadIdx.x;
    const int wid = tid >> 5, lane = tid & 31;
    const int rl = lane >> 2, w = lane & 3;
    const int wq = wid * 16;

    for (int t = tid; t < 64*16; t += 128) {
        int r = t >> 4, c4 = t & 15;
        float4 f = *(const float4*)&Q[(size_t)(b*SEQ + i0 + r)*DM + h*DH + c4*4];
        uint4 u;
        u.x = f2tf32(f.x); u.y = f2tf32(f.y); u.z = f2tf32(f.z); u.w = f2tf32(f.w);
        *(uint4*)&Qs[r*PS + c4*4] = u;
    }

    const int vb = valid[b];
    const int iA = i0 + wq + rl;
    const int iB = iA + 8;
    const int vldA = (mode == 0) ? min(vb, iA + 1) : vb;
    const int vldB = (mode == 0) ? min(vb, iB + 1) : vb;

    for (int j0 = 0; j0 < SEQ; j0 += 64) {
        __syncthreads();
        for (int t = tid; t < 64*16; t += 128) {
            int r = t >> 4, c4 = t & 15;
            float4 f = *(const float4*)&Kv[(size_t)(b*SEQ + j0 + r)*DM + h*DH + c4*4];
            uint4 u;
            u.x = f2tf32(f.x); u.y = f2tf32(f.y); u.z = f2tf32(f.z); u.w = f2tf32(f.w);
            *(uint4*)&KVs[r*PS + c4*4] = u;
        }
        __syncthreads();

        float acc[8][4];
        #pragma unroll
        for (int nt = 0; nt < 8; nt++)
            #pragma unroll
            for (int t = 0; t < 4; t++) acc[nt][t] = 0.f;

        #pragma unroll
        for (int kk = 0; kk < 8; kk++) {
            int k0 = kk * 8;
            uint32_t a0 = Qs[(wq + rl    )*PS + k0 + w];
            uint32_t a1 = Qs[(wq + rl + 8)*PS + k0 + w];
            uint32_t a2 = Qs[(wq + rl    )*PS + k0 + w + 4];
            uint32_t a3 = Qs[(wq + rl + 8)*PS + k0 + w + 4];
            #pragma unroll
            for (int nt = 0; nt < 8; nt++) {
                uint32_t b0 = KVs[(nt*8 + rl)*PS + k0 + w];
                uint32_t b1 = KVs[(nt*8 + rl)*PS + k0 + w + 4];
                mma_tf32(acc[nt], a0, a1, a2, a3, b0, b1);
            }
        }

        #pragma unroll
        for (int nt = 0; nt < 8; nt++) {
            int j = j0 + nt*8 + w*2;
            float2 v0, v1;
            v0.x = (j     >= vldA) ? 1e-6f : acc[nt][0]*0.125f;
            v0.y = (j + 1 >= vldA) ? 1e-6f : acc[nt][1]*0.125f;
            v1.x = (j     >= vldB) ? 1e-6f : acc[nt][2]*0.125f;
            v1.y = (j + 1 >= vldB) ? 1e-6f : acc[nt][3]*0.125f;
            *(float2*)&Sc[(wq + rl    )*PSC + j] = v0;
            *(float2*)&Sc[(wq + rl + 8)*PSC + j] = v1;
        }
    }
    __syncthreads();

    for (int rr = 0; rr < 16; rr++) {
        float* p = Sc + (wq + rr)*PSC;
        float vals[8];
        float mx = -1e30f;
        #pragma unroll
        for (int t = 0; t < 8; t++) { vals[t] = p[lane + t*32]; mx = fmaxf(mx, vals[t]); }
        #pragma unroll
        for (int o = 16; o; o >>= 1) mx = fmaxf(mx, __shfl_xor_sync(0xffffffffu, mx, o));
        float sum = 0.f;
        #pragma unroll
        for (int t = 0; t < 8; t++) { vals[t] = expf(vals[t] - mx); sum += vals[t]; }
        #pragma unroll
        for (int o = 16; o; o >>= 1) sum += __shfl_xor_sync(0xffffffffu, sum, o);
        float inv = 1.0f / sum;
        #pragma unroll
        for (int t = 0; t < 8; t++) p[lane + t*32] = vals[t] * inv;
    }

    float oacc[8][4];
    #pragma unroll
    for (int nt = 0; nt < 8; nt++)
        #pragma unroll
        for (int t = 0; t < 4; t++) oacc[nt][t] = 0.f;

    for (int j0 = 0; j0 < SEQ; j0 += 64) {
        __syncthreads();
        for (int t = tid; t < 64*16; t += 128) {
            int j = t >> 4, c4 = t & 15;
            float4 f = *(const float4*)&Vv[(size_t)(b*SEQ + j0 + j)*DM + h*DH + c4*4];
            int d0 = c4*4;
            KVs[(d0  )*PS + (j ^ (((d0  )>>2)&15))] = f2tf32(f.x);
            KVs[(d0+1)*PS + (j ^ (((d0+1)>>2)&15))] = f2tf32(f.y);
            KVs[(d0+2)*PS + (j ^ (((d0+2)>>2)&15))] = f2tf32(f.z);
            KVs[(d0+3)*PS + (j ^ (((d0+3)>>2)&15))] = f2tf32(f.w);
        }
        __syncthreads();

        #pragma unroll
        for (int kk = 0; kk < 8; kk++) {
            int k0 = kk * 8;
            uint32_t a0 = f2tf32(Sc[(wq + rl    )*PSC + j0 + k0 + w]);
            uint32_t a1 = f2tf32(Sc[(wq + rl + 8)*PSC + j0 + k0 + w]);
            uint32_t a2 = f2tf32(Sc[(wq + rl    )*PSC + j0 + k0 + w + 4]);
            uint32_t a3 = f2tf32(Sc[(wq + rl + 8)*PSC + j0 + k0 + w + 4]);
            #pragma unroll
            for (int nt = 0; nt < 8; nt++) {
                int d  = nt*8 + rl;
                int fx = (d >> 2) & 15;
                uint32_t b0 = KVs[d*PS + ((k0 + w    ) ^ fx)];
                uint32_t b1 = KVs[d*PS + ((k0 + w + 4) ^ fx)];
                mma_tf32(oacc[nt], a0, a1, a2, a3, b0, b1);
            }
        }
    }

    #pragma unroll
    for (int nt = 0; nt < 8; nt++) {
        int d = nt*8 + w*2;
        *(float2*)&O[(size_t)(b*SEQ + iA)*DM + h*DH + d] = make_float2(oacc[nt][0], oacc[nt][1]);
        *(float2*)&O[(size_t)(b*SEQ + iB)*DM + h*DH + d] = make_float2(oacc[nt][2], oacc[nt][3]);
    }
}

// ---------------- out = LayerNorm(a + r0 + r1) * g + be ----------------
__global__ void add_ln3_kernel(const float* __restrict__ a, const float* __restrict__ r0,
                               const float* __restrict__ r1,
                               const float* __restrict__ g, const float* __restrict__ be,
                               float* __restrict__ out)
{
    int row = blockIdx.x;
    __shared__ float red[256];
    float x[4];
    #pragma unroll
    for (int t = 0; t < 4; t++) {
        int c = threadIdx.x + t*256;
        x[t] = a[row*DM + c] + r0[row*DM + c] + r1[row*DM + c];
    }
    float s = x[0] + x[1] + x[2] + x[3];
    red[threadIdx.x] = s; __syncthreads();
    for (int o = 128; o; o >>= 1) {
        if (threadIdx.x < o) red[threadIdx.x] += red[threadIdx.x + o];
        __syncthreads();
    }
    float mean = red[0] * (1.0f / DM);
    __syncthreads();
    float vs = 0.f;
    #pragma unroll
    for (int t = 0; t < 4; t++) { float d = x[t] - mean; vs += d*d; }
    red[threadIdx.x] = vs; __syncthreads();
    for (int o = 128; o; o >>= 1) {
        if (threadIdx.x < o) red[threadIdx.x] += red[threadIdx.x + o];
        __syncthreads();
    }
    float inv = rsqrtf(red[0] * (1.0f / DM) + 1e-5f);
    #pragma unroll
    for (int t = 0; t < 4; t++) {
        int c = threadIdx.x + t*256;
        out[row*DM + c] = (x[t] - mean) * inv * g[c] + be[c];
    }
}

// ---------------- host orchestration ----------------
extern "C" void kernel_launch(void* const* d_in, const int* in_sizes, int n_in,
                              void* d_out, int out_size)
{
    const int*   X         = (const int*)  d_in[0];
    const int*   dec_valid = (const int*)  d_in[1];
    const float* enc_out   = (const float*)d_in[2];
    const int*   enc_valid = (const int*)  d_in[3];
    const float* emb       = (const float*)d_in[4];
    const float* Wq1 = (const float*)d_in[5];
    const float* Wk1 = (const float*)d_in[6];
    const float* Wv1 = (const float*)d_in[7];
    const float* Wo1 = (const float*)d_in[8];
    const float* Wq2 = (const float*)d_in[9];
    const float* Wk2 = (const float*)d_in[10];
    const float* Wv2 = (const float*)d_in[11];
    const float* Wo2 = (const float*)d_in[12];
    const float* W1  = (const float*)d_in[13];
    const float* W2  = (const float*)d_in[14];
    const float* Wout= (const float*)d_in[15];
    const float* b1  = (const float*)d_in[16];
    const float* b2  = (const float*)d_in[17];
    const float* bout= (const float*)d_in[18];
    const float* ln1g= (const float*)d_in[19];
    const float* ln1b= (const float*)d_in[20];
    const float* ln2g= (const float*)d_in[21];
    const float* ln2b= (const float*)d_in[22];
    const float* ln3g= (const float*)d_in[23];
    const float* ln3b= (const float*)d_in[24];
    float* out = (float*)d_out;

    float *h, *q, *k, *v, *attn, *proj, *proj2, *y, *y2, *ffn, *k2, *v2;
    cudaGetSymbolAddress((void**)&h,     g_h);
    cudaGetSymbolAddress((void**)&q,     g_q);
    cudaGetSymbolAddress((void**)&k,     g_k);
    cudaGetSymbolAddress((void**)&v,     g_v);
    cudaGetSymbolAddress((void**)&attn,  g_attn);
    cudaGetSymbolAddress((void**)&proj,  g_proj);
    cudaGetSymbolAddress((void**)&proj2, g_proj2);
    cudaGetSymbolAddress((void**)&y,     g_y);
    cudaGetSymbolAddress((void**)&y2,    g_y2);
    cudaGetSymbolAddress((void**)&ffn,   g_ffn);
    cudaGetSymbolAddress((void**)&k2,    g_k2);
    cudaGetSymbolAddress((void**)&v2,    g_v2);

    __half *wq1h, *wk1h, *wv1h, *wo1h, *wq2h, *wk2h, *wv2h, *wo2h, *w1h, *w2h, *wouth;
    cudaGetSymbolAddress((void**)&wq1h, g_wq1h);
    cudaGetSymbolAddress((void**)&wk1h, g_wk1h);
    cudaGetSymbolAddress((void**)&wv1h, g_wv1h);
    cudaGetSymbolAddress((void**)&wo1h, g_wo1h);
    cudaGetSymbolAddress((void**)&wq2h, g_wq2h);
    cudaGetSymbolAddress((void**)&wk2h, g_wk2h);
    cudaGetSymbolAddress((void**)&wv2h, g_wv2h);
    cudaGetSymbolAddress((void**)&wo2h, g_wo2h);
    cudaGetSymbolAddress((void**)&w1h,  g_w1h);
    cudaGetSymbolAddress((void**)&w2h,  g_w2h);
    cudaGetSymbolAddress((void**)&wouth,g_wouth);

    static int attr_set = 0;
    if (!attr_set) {
        cudaFuncSetAttribute(flash_attn_kernel,
                             cudaFuncAttributeMaxDynamicSharedMemorySize, FLASH_SMEM);
        attr_set = 1;
    }

    // ---- weight transpose+convert ----
    {
        dim3 tb(32, 8);
        dim3 gsq(DM/32, DM/32, NL);
        size_t sq = (size_t)DM*DM;
        transpose_h_kernel<<<gsq, tb>>>(Wq1, wq1h, DM, DM, sq, sq);
        transpose_h_kernel<<<gsq, tb>>>(Wk1, wk1h, DM, DM, sq, sq);
        transpose_h_kernel<<<gsq, tb>>>(Wv1, wv1h, DM, DM, sq, sq);
        transpose_h_kernel<<<gsq, tb>>>(Wo1, wo1h, DM, DM, sq, sq);
        transpose_h_kernel<<<gsq, tb>>>(Wq2, wq2h, DM, DM, sq, sq);
        transpose_h_kernel<<<gsq, tb>>>(Wk2, wk2h, DM, DM, sq, sq);
        transpose_h_kernel<<<gsq, tb>>>(Wv2, wv2h, DM, DM, sq, sq);
        transpose_h_kernel<<<gsq, tb>>>(Wo2, wo2h, DM, DM, sq, sq);
        size_t rct = (size_t)DM*HID;
        transpose_h_kernel<<<dim3(HID/32, DM/32, NL), tb>>>(W1, w1h, DM, HID, rct, rct);
        transpose_h_kernel<<<dim3(DM/32, HID/32, NL), tb>>>(W2, w2h, HID, DM, rct, rct);
        transpose_h_kernel<<<dim3(VOCAB/32, DM/32, 1), tb>>>(Wout, wouth, DM, VOCAB, 0, 0);
    }

    embed_kernel<<<ROWS, 256>>>(X, emb, h);

    // hoisted cross-attention K/V projections for ALL layers
    {
        PtrsN P;
        for (int l = 0; l < NL; l++) {
            P.B[l*2  ] = wk2h + (size_t)l*DM*DM;
            P.B[l*2+1] = wv2h + (size_t)l*DM*DM;
            P.C[l*2  ] = k2 + (size_t)l*ROWS*DM;
            P.C[l*2+1] = v2 + (size_t)l*ROWS*DM;
        }
        hgemm_big(enc_out, P, nullptr, 2*NL, ROWS, DM, DM, 0);
    }

    dim3 fgrid(SEQ/64, BZ*NH);

    for (int l = 0; l < NL; l++) {
        const size_t o2 = (size_t)l*DM*DM;
        // ---- self attention ----
        {
            PtrsN P;
            P.B[0]=wq1h+o2; P.B[1]=wk1h+o2; P.B[2]=wv1h+o2;
            P.C[0]=q;       P.C[1]=k;       P.C[2]=v;
            hgemm_big(h, P, nullptr, 3, ROWS, DM, DM, 0);
        }
        flash_attn_kernel<<<fgrid, 128, FLASH_SMEM>>>(q, k, v, attn, dec_valid, 0);
        hgemm64ks(attn, wo1h+o2, nullptr, proj, proj2, ROWS, DM, DM);
        add_ln3_kernel<<<ROWS, 256>>>(h, proj, proj2, ln1g + l*DM, ln1b + l*DM, y);
        // ---- cross attention (K/V precomputed) ----
        hgemm64(y, wq2h+o2, nullptr, q, ROWS, DM, DM, 0);
        flash_attn_kernel<<<fgrid, 128, FLASH_SMEM>>>(
            q, k2 + (size_t)l*ROWS*DM, v2 + (size_t)l*ROWS*DM, attn, enc_valid, 1);
        hgemm64ks(attn, wo2h+o2, nullptr, proj, proj2, ROWS, DM, DM);
        add_ln3_kernel<<<ROWS, 256>>>(y, proj, proj2, ln2g + l*DM, ln2b + l*DM, y2);
        // ---- FFN ----
        {
            PtrsN P;
            P.B[0] = w1h + (size_t)l*HID*DM;
            P.C[0] = ffn;
            hgemm_big(y2, P, b1 + l*HID, 1, ROWS, HID, DM, 1);
        }
        hgemm64ks(ffn, w2h + (size_t)l*DM*HID, b2 + l*DM, proj, proj2, ROWS, DM, HID);
        add_ln3_kernel<<<ROWS, 256>>>(y2, proj, proj2, ln3g + l*DM, ln3b + l*DM, h);
    }
    // ---- final vocab projection ----
    {
        PtrsN P;
        P.B[0] = wouth;
        P.C[0] = out;
        hgemm_big(h, P, bout, 1, ROWS, VOCAB, DM, 0);
    }
}